// round 1
// baseline (speedup 1.0000x reference)
#include <cuda_runtime.h>
#include <math.h>

#define BB 8
#define TT 5
#define HH 512
#define WW 512
#define HW (HH*WW)
#define MID 16
#define NPIX (BB*HW)

// ---------------- scratch (no allocation allowed) ----------------
__device__ float g_acc[NPIX];                 // 8 MB
__device__ float g_h1[(size_t)NPIX*MID];      // 134 MB
__device__ float g_h2[(size_t)NPIX*MID];      // 134 MB
__device__ double g_dsum, g_dssq;
__device__ float g_mean, g_inv;
__device__ float g_w1f[144], g_s1[16];
__device__ float g_w2f[2304], g_s2[16];
__device__ float g_w3f[2304], g_s3[16];

// ---------------- prep: zero stats + fold BN into conv weights ----------------
__global__ void prep_kernel(
    const float* __restrict__ w1, const float* __restrict__ g1, const float* __restrict__ b1,
    const float* __restrict__ rm1, const float* __restrict__ rv1,
    const float* __restrict__ w2, const float* __restrict__ g2, const float* __restrict__ b2,
    const float* __restrict__ rm2, const float* __restrict__ rv2,
    const float* __restrict__ w3, const float* __restrict__ g3, const float* __restrict__ b3,
    const float* __restrict__ rm3, const float* __restrict__ rv3)
{
    int tid = threadIdx.x;
    if (tid == 0) { g_dsum = 0.0; g_dssq = 0.0; }

    // conv1: sum over T input channels (motion broadcast), fold BN scale
    for (int i = tid; i < 144; i += 256) {
        int o = i / 9, k = i % 9;
        float sc = g1[o] / sqrtf(rv1[o] + 1e-5f);
        float s = 0.f;
        #pragma unroll
        for (int t = 0; t < TT; t++) s += w1[(o * TT + t) * 9 + k];
        g_w1f[i] = sc * s;
    }
    if (tid < 16) {
        float sc1 = g1[tid] / sqrtf(rv1[tid] + 1e-5f);
        g_s1[tid] = b1[tid] - rm1[tid] * sc1;
        float sc2 = g2[tid] / sqrtf(rv2[tid] + 1e-5f);
        g_s2[tid] = b2[tid] - rm2[tid] * sc2;
        float sc3 = g3[tid] / sqrtf(rv3[tid] + 1e-5f);
        g_s3[tid] = b3[tid] - rm3[tid] * sc3;
    }
    // conv2/conv3 folded weights in [tap][ci][co] layout (co contiguous for LDS.128)
    for (int i = tid; i < 2304; i += 256) {
        int k = i >> 8, ci = (i >> 4) & 15, co = i & 15;
        float sc2 = g2[co] / sqrtf(rv2[co] + 1e-5f);
        g_w2f[i] = sc2 * w2[(co * 16 + ci) * 9 + k];
        float sc3 = g3[co] / sqrtf(rv3[co] + 1e-5f);
        g_w3f[i] = sc3 * w3[(co * 16 + ci) * 9 + k];
    }
}

// ---------------- A: acc = sum|raw_diff| + mean/var reduction ----------------
__global__ void accum_kernel(const float* __restrict__ rd)
{
    int i = blockIdx.x * 256 + threadIdx.x;        // over NPIX/4 = 524288
    int b = i >> 16;                               // HW/4 = 65536 float4 per image
    int r = i & 65535;
    const float4* p = (const float4*)rd;
    float4 a = make_float4(0.f, 0.f, 0.f, 0.f);
    #pragma unroll
    for (int t = 0; t < TT - 1; t++) {
        float4 v = p[((size_t)(b * (TT - 1) + t)) * 65536 + r];
        a.x += fabsf(v.x); a.y += fabsf(v.y); a.z += fabsf(v.z); a.w += fabsf(v.w);
    }
    ((float4*)g_acc)[i] = a;

    double ls  = (double)a.x + (double)a.y + (double)a.z + (double)a.w;
    double lss = (double)a.x * a.x + (double)a.y * a.y + (double)a.z * a.z + (double)a.w * a.w;
    #pragma unroll
    for (int o = 16; o > 0; o >>= 1) {
        ls  += __shfl_down_sync(0xffffffffu, ls,  o);
        lss += __shfl_down_sync(0xffffffffu, lss, o);
    }
    __shared__ double ss[8], sq[8];
    int wid = threadIdx.x >> 5, lane = threadIdx.x & 31;
    if (lane == 0) { ss[wid] = ls; sq[wid] = lss; }
    __syncthreads();
    if (threadIdx.x == 0) {
        double s = 0.0, q = 0.0;
        #pragma unroll
        for (int w = 0; w < 8; w++) { s += ss[w]; q += sq[w]; }
        atomicAdd(&g_dsum, s);
        atomicAdd(&g_dssq, q);
    }
}

__global__ void finalize_kernel()
{
    double n = (double)NPIX;
    double mean = g_dsum / n;
    double var = (g_dssq - g_dsum * g_dsum / n) / (n - 1.0);
    double sd = sqrt(var);
    g_mean = (float)mean;
    g_inv = (float)(1.0 / (sd + 1e-6));
}

// ---------------- conv1: 1->16 chan, 3x3 d1, normalize-on-load, BN+ReLU ----------------
__global__ void conv1_kernel()
{
    __shared__ float sw[144], sb[16];
    int tid = threadIdx.x;
    if (tid < 144) sw[tid] = g_w1f[tid];
    if (tid < 16)  sb[tid] = g_s1[tid];
    __syncthreads();

    int p = blockIdx.x * 256 + tid;
    int b = p >> 18;
    int rem = p & (HW - 1);
    int y = rem >> 9, x = rem & 511;
    float mean = g_mean, inv = g_inv;

    float m[9];
    #pragma unroll
    for (int ky = 0; ky < 3; ky++) {
        #pragma unroll
        for (int kx = 0; kx < 3; kx++) {
            int yy = y + ky - 1, xx = x + kx - 1;
            bool ok = (yy >= 0) & (yy < HH) & (xx >= 0) & (xx < WW);
            m[ky * 3 + kx] = ok ? (g_acc[(b << 18) + (yy << 9) + xx] - mean) * inv : 0.f;
        }
    }
    float v[16];
    #pragma unroll
    for (int o = 0; o < 16; o++) {
        float s = sb[o];
        #pragma unroll
        for (int k = 0; k < 9; k++) s = fmaf(sw[o * 9 + k], m[k], s);
        v[o] = fmaxf(s, 0.f);
    }
    float4* out = (float4*)(g_h1 + (size_t)p * 16);
    out[0] = make_float4(v[0],  v[1],  v[2],  v[3]);
    out[1] = make_float4(v[4],  v[5],  v[6],  v[7]);
    out[2] = make_float4(v[8],  v[9],  v[10], v[11]);
    out[3] = make_float4(v[12], v[13], v[14], v[15]);
}

// ---------------- conv2/conv3: 16->16 chan, 3x3 dilated, BN+ReLU, NHWC ----------------
// 2 pixels (x, x+32) per thread; weights in smem, co-contiguous -> LDS.128
template<int DIL>
__global__ __launch_bounds__(128) void conv16_kernel()
{
    const float* __restrict__ in  = (DIL == 2) ? g_h1 : g_h2;
    float*       __restrict__ out = (DIL == 2) ? g_h2 : g_h1;
    const float* wf = (DIL == 2) ? g_w2f : g_w3f;
    const float* sh = (DIL == 2) ? g_s2  : g_s3;

    __shared__ float sw[2304];
    __shared__ float sb[16];
    int tid = threadIdx.y * 32 + threadIdx.x;
    for (int i = tid; i < 2304; i += 128) sw[i] = wf[i];
    if (tid < 16) sb[tid] = sh[tid];
    __syncthreads();

    int x0 = blockIdx.x * 64 + threadIdx.x;
    int y  = blockIdx.y * 4 + threadIdx.y;
    int b  = blockIdx.z;

    float a0[16], a1[16];
    #pragma unroll
    for (int c = 0; c < 16; c++) { a0[c] = 0.f; a1[c] = 0.f; }

    #pragma unroll
    for (int ky = 0; ky < 3; ky++) {
        int yy = y + (ky - 1) * DIL;
        if (yy < 0 || yy >= HH) continue;
        size_t rowbase = ((size_t)b << 18) + ((size_t)yy << 9);
        #pragma unroll
        for (int kx = 0; kx < 3; kx++) {
            int k = ky * 3 + kx;
            int xx0 = x0 + (kx - 1) * DIL;
            int xx1 = xx0 + 32;
            bool v0 = (xx0 >= 0) & (xx0 < WW);
            bool v1 = (xx1 >= 0) & (xx1 < WW);
            const float4* q0 = (const float4*)(in + (rowbase + xx0) * 16);
            const float4* q1 = (const float4*)(in + (rowbase + xx1) * 16);
            float f0[16], f1[16];
            #pragma unroll
            for (int c = 0; c < 4; c++) {
                float4 t0 = v0 ? q0[c] : make_float4(0.f, 0.f, 0.f, 0.f);
                float4 t1 = v1 ? q1[c] : make_float4(0.f, 0.f, 0.f, 0.f);
                f0[4 * c + 0] = t0.x; f0[4 * c + 1] = t0.y; f0[4 * c + 2] = t0.z; f0[4 * c + 3] = t0.w;
                f1[4 * c + 0] = t1.x; f1[4 * c + 1] = t1.y; f1[4 * c + 2] = t1.z; f1[4 * c + 3] = t1.w;
            }
            const float* wk = sw + k * 256;
            #pragma unroll
            for (int ci = 0; ci < 16; ci++) {
                float u0 = f0[ci], u1 = f1[ci];
                const float* wr = wk + ci * 16;
                #pragma unroll
                for (int co = 0; co < 16; co++) {
                    float w = wr[co];
                    a0[co] = fmaf(w, u0, a0[co]);
                    a1[co] = fmaf(w, u1, a1[co]);
                }
            }
        }
    }

    size_t ob = ((size_t)b << 18) + ((size_t)y << 9);
    float4* o0 = (float4*)(out + (ob + x0) * 16);
    float4* o1 = (float4*)(out + (ob + x0 + 32) * 16);
    #pragma unroll
    for (int c = 0; c < 4; c++) {
        o0[c] = make_float4(fmaxf(a0[4*c+0] + sb[4*c+0], 0.f), fmaxf(a0[4*c+1] + sb[4*c+1], 0.f),
                            fmaxf(a0[4*c+2] + sb[4*c+2], 0.f), fmaxf(a0[4*c+3] + sb[4*c+3], 0.f));
        o1[c] = make_float4(fmaxf(a1[4*c+0] + sb[4*c+0], 0.f), fmaxf(a1[4*c+1] + sb[4*c+1], 0.f),
                            fmaxf(a1[4*c+2] + sb[4*c+2], 0.f), fmaxf(a1[4*c+3] + sb[4*c+3], 0.f));
    }
}

// ---------------- conv4 (1x1, 16->45) + sigmoid + dynamic 3x3 filtering ----------------
__global__ __launch_bounds__(128) void final_kernel(
    const float* __restrict__ x, const float* __restrict__ w4,
    const float* __restrict__ biasp, float* __restrict__ out)
{
    __shared__ float sw[720];
    int tid = threadIdx.x;
    for (int i = tid; i < 720; i += 128) sw[i] = w4[i];
    __syncthreads();

    int p = blockIdx.x * 128 + tid;
    int b = p >> 18;
    int rem = p & (HW - 1);
    int y = rem >> 9, xc = rem & 511;

    float h[16];
    const float4* hp = (const float4*)(g_h1 + (size_t)p * 16);
    #pragma unroll
    for (int c = 0; c < 4; c++) {
        float4 t = hp[c];
        h[4*c+0] = t.x; h[4*c+1] = t.y; h[4*c+2] = t.z; h[4*c+3] = t.w;
    }
    float bias = biasp[0];

    #pragma unroll
    for (int t = 0; t < TT; t++) {
        float r[9];
        #pragma unroll
        for (int j = 0; j < 9; j++) {
            const float* wr = sw + (t * 9 + j) * 16;
            float s = 0.f;
            #pragma unroll
            for (int ci = 0; ci < 16; ci++) s = fmaf(wr[ci], h[ci], s);
            r[j] = s;
        }
        const float* xb = x + ((size_t)(b * TT + t) << 18);
        float o = 0.f;
        #pragma unroll
        for (int dy = 0; dy < 3; dy++) {
            int yy = y + dy - 1;
            #pragma unroll
            for (int dx = 0; dx < 3; dx++) {
                int xx = xc + dx - 1;
                bool ok = (yy >= 0) & (yy < HH) & (xx >= 0) & (xx < WW);
                float xv = ok ? xb[(yy << 9) + xx] : 0.f;
                float z = r[dy * 3 + dx] + bias;
                float ker = 10.f / (1.f + __expf(-z)) + 0.1f;
                o = fmaf(ker, xv, o);
            }
        }
        out[((size_t)(b * TT + t) << 18) + rem] = o;
    }
}

// ---------------- launch ----------------
extern "C" void kernel_launch(void* const* d_in, const int* in_sizes, int n_in,
                              void* d_out, int out_size)
{
    const float* x_aligned = (const float*)d_in[0];
    const float* raw_diff  = (const float*)d_in[1];
    const float* w1  = (const float*)d_in[2];
    const float* g1  = (const float*)d_in[3];
    const float* b1  = (const float*)d_in[4];
    const float* rm1 = (const float*)d_in[5];
    const float* rv1 = (const float*)d_in[6];
    const float* w2  = (const float*)d_in[7];
    const float* g2  = (const float*)d_in[8];
    const float* b2  = (const float*)d_in[9];
    const float* rm2 = (const float*)d_in[10];
    const float* rv2 = (const float*)d_in[11];
    const float* w3  = (const float*)d_in[12];
    const float* g3  = (const float*)d_in[13];
    const float* b3  = (const float*)d_in[14];
    const float* rm3 = (const float*)d_in[15];
    const float* rv3 = (const float*)d_in[16];
    const float* w4  = (const float*)d_in[17];
    const float* bias = (const float*)d_in[18];
    float* out = (float*)d_out;

    prep_kernel<<<1, 256>>>(w1, g1, b1, rm1, rv1, w2, g2, b2, rm2, rv2,
                            w3, g3, b3, rm3, rv3);
    accum_kernel<<<NPIX / 4 / 256, 256>>>(raw_diff);
    finalize_kernel<<<1, 1>>>();
    conv1_kernel<<<NPIX / 256, 256>>>();
    {
        dim3 blk(32, 4);
        dim3 grd(WW / 64, HH / 4, BB);
        conv16_kernel<2><<<grd, blk>>>();
        conv16_kernel<4><<<grd, blk>>>();
    }
    final_kernel<<<NPIX / 128, 128>>>(x_aligned, w4, bias, out);
}